// round 2
// baseline (speedup 1.0000x reference)
#include <cuda_runtime.h>
#include <math.h>

#define NN 10000
#define EORIG 50000
#define EDOUB 100000
#define BB 4
#define NT 40000
#define DD 64
#define KS_N 4000u
#define ES_E 40000u

// ------------------------- device scratch -------------------------
__device__ float g_hidden[NT * DD];
__device__ float g_score[NT];
__device__ float g_x[NT * DD];
__device__ float g_feat[NT * 256];
__device__ float g_C[NT * 192];
__device__ float g_Wcat[3 * 256 * 192];
__device__ float g_qpart[DD];
__device__ float g_deg[NT];
__device__ int   g_ptr[NN + 1];
__device__ int   g_cur[NN];
__device__ int   g_cnt[NN];
__device__ int   g_adj[EDOUB];
__device__ int   g_wlist[NT];
__device__ unsigned g_bins0[65536];
__device__ unsigned g_bins1[65536];
__device__ float g_pna;
__device__ float g_thr;   // node threshold (rank-4000 score)
__device__ float g_T;     // effective threshold for edge mask
__device__ unsigned g_digit, g_krem, g_skip;
__device__ int g_wl;

// ------------------------- helpers -------------------------
__device__ __forceinline__ unsigned f2key(float f) {
    unsigned u = __float_as_uint(f);
    return (u & 0x80000000u) ? ~u : (u | 0x80000000u);
}
__device__ __forceinline__ float key2f(unsigned key) {
    unsigned u = (key & 0x80000000u) ? (key & 0x7FFFFFFFu) : ~key;
    return __uint_as_float(u);
}

// warp-aggregated weighted histogram add (handles massive ties in layer 0)
__device__ __forceinline__ void warpHistAdd(unsigned* bins, unsigned bin, unsigned w) {
    unsigned m = __match_any_sync(0xffffffffu, bin);
    int lane = threadIdx.x & 31;
    int leader = __ffs(m) - 1;
    unsigned tot = 0;
    #pragma unroll
    for (int j = 0; j < 32; j++) {
        unsigned bj = __shfl_sync(0xffffffffu, bin, j);
        unsigned wj = __shfl_sync(0xffffffffu, w, j);
        if (bj == bin) tot += wj;
    }
    if (bin <= 0xFFFFu && lane == leader && tot > 0) atomicAdd(&bins[bin], tot);
}

// ------------------------- setup kernels -------------------------
__global__ void k_init() {
    int i = blockIdx.x * blockDim.x + threadIdx.x;
    if (i < NT) g_score[i] = 0.0f;
    if (i < NN) g_cnt[i] = 0;
    if (i == 0) g_wl = 0;
}

__global__ void k_count(const int* __restrict__ ei) {
    int e = blockIdx.x * blockDim.x + threadIdx.x;
    if (e >= EDOUB) return;
    int dst = ei[(e + EORIG) % EDOUB];
    atomicAdd(&g_cnt[dst], 1);
}

__global__ void k_scan() {  // 1 block, 1024 threads
    __shared__ unsigned cs[1024];
    __shared__ float ps[1024];
    int t = threadIdx.x;
    unsigned loc[10];
    unsigned s = 0; float pl = 0.0f;
    #pragma unroll
    for (int i = 0; i < 10; i++) {
        int idx = t * 10 + i;
        unsigned c = (idx < NN) ? (unsigned)g_cnt[idx] : 0u;
        loc[i] = c; s += c;
        if (idx < NN) pl += logf((float)c + 1.0f);
    }
    cs[t] = s; ps[t] = pl;
    __syncthreads();
    for (int off = 1; off < 1024; off <<= 1) {
        unsigned v = (t >= off) ? cs[t - off] : 0u;
        __syncthreads();
        cs[t] += v;
        __syncthreads();
    }
    unsigned run = cs[t] - s;
    #pragma unroll
    for (int i = 0; i < 10; i++) {
        int idx = t * 10 + i;
        if (idx < NN) { g_ptr[idx] = (int)run; g_cur[idx] = (int)run; run += loc[i]; }
    }
    if (t == 1023) g_ptr[NN] = (int)cs[1023];
    for (int off = 512; off > 0; off >>= 1) {
        __syncthreads();
        if (t < off) ps[t] += ps[t + off];
    }
    __syncthreads();
    if (t == 0) g_pna = ps[0] / (float)NN;
}

__global__ void k_scatter(const int* __restrict__ ei, const int* __restrict__ ea) {
    int e = blockIdx.x * blockDim.x + threadIdx.x;
    if (e >= EDOUB) return;
    int src = ei[e];
    int dst = ei[(e + EORIG) % EDOUB];
    int a   = ea[e % EORIG];
    int pos = atomicAdd(&g_cur[dst], 1);
    g_adj[pos] = src | (a << 16);
}

__global__ void k_inithidden(const float* __restrict__ text,
                             const int* __restrict__ h_index,
                             const float* __restrict__ hstates) {
    int idx = blockIdx.x * blockDim.x + threadIdx.x;
    if (idx >= NT * DD) return;
    int v = idx >> 6, d = idx & 63;
    float val = (v < NN) ? text[v * DD + d] : 0.0f;
    int b = v / NN;
    int h0b = h_index[b * 16] + b * NN;
    if (v == h0b) val = hstates[b * DD + d];
    g_hidden[idx] = val;
}

__global__ void k_repack(const float* __restrict__ convW) {
    int idx = blockIdx.x * blockDim.x + threadIdx.x;
    if (idx >= 3 * 256 * 192) return;
    int l = idx / 49152;
    int rem = idx % 49152;
    int kk = rem / 192, j = rem % 192;
    int g = j >> 6, c = j & 63;
    g_Wcat[idx] = convW[(l * 768 + g * 256 + kk) * 64 + c];
}

__global__ void k_qpart(const int* __restrict__ r_index,
                        const float* __restrict__ relT,
                        const float* __restrict__ Wlin,
                        const float* __restrict__ blin) {
    int j = threadIdx.x;
    if (j >= DD) return;
    int r0 = r_index[0];
    float acc = blin[j];
    for (int d = 0; d < DD; d++)
        acc += relT[r0 * DD + d] * Wlin[(DD + d) * DD + j];
    g_qpart[j] = acc;
}

__global__ void k_headscore(const int* __restrict__ h_index,
                            const int* __restrict__ r_index,
                            const float* __restrict__ hstates,
                            const float* __restrict__ relT,
                            const float* __restrict__ Wlin,
                            const float* __restrict__ blin,
                            const float* __restrict__ W1,
                            const float* __restrict__ b1,
                            const float* __restrict__ W2,
                            const float* __restrict__ b2) {
    __shared__ float sx[4][64];
    int t = threadIdx.x;      // 128 threads = 4 warps
    int b = t >> 5, ln = t & 31;
    int r0 = r_index[b * 16];
    int h0b = h_index[b * 16] + b * NN;
    const float* hv = hstates + b * DD;
    const float* rv = relT + r0 * DD;
    #pragma unroll
    for (int half = 0; half < 2; half++) {
        int c = ln + half * 32;
        float acc = blin[c];
        for (int d = 0; d < DD; d++)
            acc += hv[d] * Wlin[d * DD + c] + rv[d] * Wlin[(DD + d) * DD + c];
        sx[b][c] = hv[c] * acc;
    }
    __syncwarp();
    float sp = 0.0f;
    #pragma unroll
    for (int oo = 0; oo < 4; oo++) {
        int o = ln * 4 + oo;
        float a2 = b1[o];
        for (int d = 0; d < DD; d++) a2 += sx[b][d] * W1[d * 128 + o];
        a2 = fmaxf(a2, 0.0f);
        sp += a2 * W2[o];
    }
    #pragma unroll
    for (int off = 16; off > 0; off >>= 1)
        sp += __shfl_down_sync(0xffffffffu, sp, off);
    if (ln == 0) g_score[h0b] = sp + b2[0];
}

// ------------------------- selection kernels -------------------------
__global__ void k_zero() {
    int i = blockIdx.x * blockDim.x + threadIdx.x;
    if (i < 65536) { g_bins0[i] = 0; g_bins1[i] = 0; }
}

// phase: 1 = high16 into bins0, 2 = low16 (of selected high) into bins1
// isEdge: 0 = node select (w=1), 1 = edge select (filter score>=g_thr, w=deg)
__global__ void k_hist(int phase, int isEdge) {
    int i = blockIdx.x * blockDim.x + threadIdx.x;
    unsigned bin = 0x10000u, w = 0;
    if (i < NT) {
        float sc = g_score[i];
        bool ok = true;
        if (isEdge) ok = (sc >= g_thr);
        if (ok) {
            unsigned key = f2key(sc);
            unsigned b;
            if (phase == 1) b = key >> 16;
            else b = ((key >> 16) == g_digit) ? (key & 0xFFFFu) : 0x10000u;
            if (b <= 0xFFFFu) {
                bin = b;
                if (isEdge) {
                    int lv = i - (i / NN) * NN;
                    w = (unsigned)(g_ptr[lv + 1] - g_ptr[lv]);
                } else w = 1;
            }
        }
    }
    unsigned* bins = (phase == 1) ? g_bins0 : g_bins1;
    warpHistAdd(bins, bin, w);
}

__global__ void k_pick(int phase, int isEdge, unsigned kparam) {  // 1 block, 1024 thr
    __shared__ unsigned ss[1024];
    int t = threadIdx.x;
    if (isEdge && phase == 2 && g_skip) {
        if (t == 0) g_wl = 0;
        return;
    }
    unsigned kk = (phase == 1) ? kparam : g_krem;
    const unsigned* bins = (phase == 1) ? g_bins0 : g_bins1;
    int base = t * 64;
    unsigned s = 0;
    for (int i = 0; i < 64; i++) s += bins[base + i];
    ss[t] = s;
    __syncthreads();
    for (int off = 1; off < 1024; off <<= 1) {
        unsigned v = (t + off < 1024) ? ss[t + off] : 0u;
        __syncthreads();
        ss[t] += v;
        __syncthreads();
    }
    unsigned inc = ss[t];
    unsigned exc = inc - s;
    unsigned total = ss[0];
    if (isEdge && phase == 1) {
        if (total < kparam) {
            if (t == 0) { g_skip = 1; g_T = g_thr; }
            return;
        }
        if (t == 0) g_skip = 0;
    }
    if (exc < kk && inc >= kk) {
        unsigned c = exc;
        for (int i = 63; i >= 0; i--) {
            unsigned bv = bins[base + i];
            if (c + bv >= kk) {
                if (phase == 1) { g_digit = (unsigned)(base + i); g_krem = kk - c; }
                else {
                    unsigned key = (g_digit << 16) | (unsigned)(base + i);
                    float val = key2f(key);
                    if (!isEdge) g_thr = val; else g_T = val;
                }
                break;
            }
            c += bv;
        }
    }
    if (phase == 2 && isEdge && t == 0) g_wl = 0;
}

__global__ void k_worklist() {
    int i = blockIdx.x * blockDim.x + threadIdx.x;
    bool f = false;
    if (i < NT) {
        int lv = i - (i / NN) * NN;
        f = (g_score[i] >= g_T) && (g_ptr[lv + 1] > g_ptr[lv]);
    }
    unsigned m = __ballot_sync(0xffffffffu, f);
    if (m == 0) return;
    int lane = threadIdx.x & 31;
    int leader = __ffs(m) - 1;
    int pos = 0;
    if (lane == leader) pos = atomicAdd(&g_wl, __popc(m));
    pos = __shfl_sync(0xffffffffu, pos, leader);
    if (f) g_wlist[pos + __popc(m & ((1u << lane) - 1u))] = i;
}

// ------------------------- per-layer compute -------------------------
__global__ void k_agg(const float* __restrict__ relw, int l) {
    int w = blockIdx.x * 8 + (threadIdx.x >> 5);
    int cnt = g_wl;
    if (w >= cnt) return;
    int lane = threadIdx.x & 31;
    int v = g_wlist[w];
    int b = v / NN;
    int base = b * NN;
    int lv = v - base;
    int d0 = lane, d1 = lane + 32;
    const float* rw = relw + l * 400 * DD;
    float T = g_T;
    float s0 = 0, s1 = 0, q0 = 0, q1 = 0;
    float mx0 = -INFINITY, mx1 = -INFINITY, mn0 = INFINITY, mn1 = INFINITY;
    int deg = 0;
    int p1 = g_ptr[lv + 1];
    for (int p = g_ptr[lv]; p < p1; p++) {
        int pk = g_adj[p];
        int u = pk & 0xFFFF, a = pk >> 16;
        int gu = base + u;
        float sc = g_score[gu];
        if (sc >= T) {
            float wgt = 1.0f / (1.0f + __expf(-sc));
            float m0 = wgt * g_hidden[gu * DD + d0] * rw[a * DD + d0];
            float m1 = wgt * g_hidden[gu * DD + d1] * rw[a * DD + d1];
            s0 += m0; q0 += m0 * m0; mx0 = fmaxf(mx0, m0); mn0 = fminf(mn0, m0);
            s1 += m1; q1 += m1 * m1; mx1 = fmaxf(mx1, m1); mn1 = fminf(mn1, m1);
            deg++;
        }
    }
    float fdeg = (float)deg;
    float den = fmaxf(fdeg, 1.0f);
    float me0 = s0 / den, me1 = s1 / den;
    float sd0 = sqrtf(fmaxf(q0 / den - me0 * me0, 0.0f) + 1e-6f);
    float sd1 = sqrtf(fmaxf(q1 / den - me1 * me1, 0.0f) + 1e-6f);
    if (deg == 0) { mx0 = 0; mx1 = 0; mn0 = 0; mn1 = 0; }
    float* F = g_feat + (size_t)w * 256;
    F[d0] = me0;        F[d1] = me1;
    F[64 + d0] = mx0;   F[64 + d1] = mx1;
    F[128 + d0] = mn0;  F[128 + d1] = mn1;
    F[192 + d0] = sd0;  F[192 + d1] = sd1;
    if (lane == 0) g_deg[w] = fdeg;
}

__global__ void k_gemm(int l) {  // C[cnt,192] = feat[cnt,256] @ Wcat[256,192]
    __shared__ float sA[16][64];
    __shared__ float sB[16][64];
    int cnt = g_wl;
    int rowBase = blockIdx.x * 64;
    if (rowBase >= cnt) return;
    int colBase = blockIdx.y * 64;
    int t = threadIdx.x;
    int tx = t & 15, ty = t >> 4;
    const float* Wb = g_Wcat + l * 256 * 192;
    float acc[4][4] = {};
    for (int k0 = 0; k0 < 256; k0 += 16) {
        int r = t >> 2, kg = (t & 3) * 4;
        int row = rowBase + r;
        float4 av = make_float4(0, 0, 0, 0);
        if (row < cnt) av = *(const float4*)(g_feat + (size_t)row * 256 + k0 + kg);
        sA[kg + 0][r] = av.x; sA[kg + 1][r] = av.y;
        sA[kg + 2][r] = av.z; sA[kg + 3][r] = av.w;
        int kb = t >> 4, j4 = (t & 15) * 4;
        float4 bv = *(const float4*)(Wb + (size_t)(k0 + kb) * 192 + colBase + j4);
        sB[kb][j4 + 0] = bv.x; sB[kb][j4 + 1] = bv.y;
        sB[kb][j4 + 2] = bv.z; sB[kb][j4 + 3] = bv.w;
        __syncthreads();
        #pragma unroll
        for (int kk = 0; kk < 16; kk++) {
            float a[4], bvv[4];
            #pragma unroll
            for (int i = 0; i < 4; i++) a[i] = sA[kk][ty * 4 + i];
            #pragma unroll
            for (int j = 0; j < 4; j++) bvv[j] = sB[kk][tx * 4 + j];
            #pragma unroll
            for (int i = 0; i < 4; i++)
                #pragma unroll
                for (int j = 0; j < 4; j++)
                    acc[i][j] += a[i] * bvv[j];
        }
        __syncthreads();
    }
    #pragma unroll
    for (int i = 0; i < 4; i++) {
        int row = rowBase + ty * 4 + i;
        if (row < cnt) {
            #pragma unroll
            for (int j = 0; j < 4; j++)
                g_C[(size_t)row * 192 + colBase + tx * 4 + j] = acc[i][j];
        }
    }
}

__global__ void k_apply(const float* __restrict__ convb, int l) {
    int idx = blockIdx.x * blockDim.x + threadIdx.x;
    int i = idx >> 6;
    if (i >= g_wl) return;
    int d = idx & 63;
    int v = g_wlist[i];
    float dg = g_deg[i];
    float sl = logf(dg + 1.0f);
    float pna = g_pna;
    float amp = sl / pna;
    float att = pna / (sl + 1e-6f);
    const float* C = g_C + (size_t)i * 192;
    float u = C[d] + amp * C[64 + d] + att * C[128 + d] + convb[l * 64 + d];
    u = fmaxf(u, 0.0f);
    g_hidden[v * DD + d] += u;
}

// x = h * (h @ Wlin[0:64] + qpart), rows from worklist
__global__ void k_score1(const float* __restrict__ Wlin) {
    __shared__ float sh[64][65];
    __shared__ float sw[64][65];
    __shared__ float sq[64];
    int cnt = g_wl;
    int rowBase = blockIdx.x * 64;
    if (rowBase >= cnt) return;
    int t = threadIdx.x;
    int tx = t & 15, ty = t >> 4;
    #pragma unroll
    for (int q = 0; q < 4; q++) {
        int lin = t + q * 256;
        int r = lin >> 4, c4 = (lin & 15) * 4;
        int i = rowBase + r;
        float4 hv = make_float4(0, 0, 0, 0);
        if (i < cnt) {
            int v = g_wlist[i];
            hv = *(const float4*)(g_hidden + (size_t)v * DD + c4);
        }
        sh[r][c4] = hv.x; sh[r][c4 + 1] = hv.y; sh[r][c4 + 2] = hv.z; sh[r][c4 + 3] = hv.w;
        float4 wv = *(const float4*)(Wlin + (size_t)r * DD + c4);
        sw[r][c4] = wv.x; sw[r][c4 + 1] = wv.y; sw[r][c4 + 2] = wv.z; sw[r][c4 + 3] = wv.w;
    }
    if (t < 64) sq[t] = g_qpart[t];
    __syncthreads();
    float acc[4][4] = {};
    for (int k = 0; k < 64; k++) {
        float a[4], b[4];
        #pragma unroll
        for (int i = 0; i < 4; i++) a[i] = sh[ty * 4 + i][k];
        #pragma unroll
        for (int j = 0; j < 4; j++) b[j] = sw[k][tx * 4 + j];
        #pragma unroll
        for (int i = 0; i < 4; i++)
            #pragma unroll
            for (int j = 0; j < 4; j++)
                acc[i][j] += a[i] * b[j];
    }
    #pragma unroll
    for (int i = 0; i < 4; i++) {
        int row = rowBase + ty * 4 + i;
        if (row < cnt) {
            #pragma unroll
            for (int j = 0; j < 4; j++) {
                int c = tx * 4 + j;
                float heur = acc[i][j] + sq[c];
                g_x[(size_t)row * DD + c] = sh[ty * 4 + i][c] * heur;
            }
        }
    }
}

// score[v] = relu(x @ W1 + b1) @ W2 + b2, rows from worklist (32 per block)
__global__ void k_score2(const float* __restrict__ W1, const float* __restrict__ b1,
                         const float* __restrict__ W2, const float* __restrict__ b2) {
    __shared__ float sx[32][65];
    __shared__ float sw1[64][128];
    __shared__ float sw2[128];
    __shared__ float ssum[32];
    int cnt = g_wl;
    int rowBase = blockIdx.x * 32;
    if (rowBase >= cnt) return;
    int t = threadIdx.x;
    #pragma unroll
    for (int q = 0; q < 2; q++) {
        int lin = t + q * 256;
        int r = lin >> 4, c4 = (lin & 15) * 4;
        int i = rowBase + r;
        float4 xv = make_float4(0, 0, 0, 0);
        if (i < cnt) xv = *(const float4*)(g_x + (size_t)i * DD + c4);
        sx[r][c4] = xv.x; sx[r][c4 + 1] = xv.y; sx[r][c4 + 2] = xv.z; sx[r][c4 + 3] = xv.w;
    }
    #pragma unroll
    for (int q = 0; q < 8; q++) {
        int lin = t + q * 256;
        int r = lin >> 5, c4 = (lin & 31) * 4;
        float4 wv = *(const float4*)(W1 + (size_t)r * 128 + c4);
        sw1[r][c4] = wv.x; sw1[r][c4 + 1] = wv.y; sw1[r][c4 + 2] = wv.z; sw1[r][c4 + 3] = wv.w;
    }
    if (t < 128) sw2[t] = W2[t];
    if (t < 32) ssum[t] = 0.0f;
    __syncthreads();
    int tx = t & 31, ty = t >> 5;       // tx: 32 col-groups of 4, ty: 8 row-groups of 4
    float acc[4][4] = {};
    for (int k = 0; k < 64; k++) {
        float a[4], b[4];
        #pragma unroll
        for (int i = 0; i < 4; i++) a[i] = sx[ty * 4 + i][k];
        #pragma unroll
        for (int j = 0; j < 4; j++) b[j] = sw1[k][tx * 4 + j];
        #pragma unroll
        for (int i = 0; i < 4; i++)
            #pragma unroll
            for (int j = 0; j < 4; j++)
                acc[i][j] += a[i] * b[j];
    }
    #pragma unroll
    for (int i = 0; i < 4; i++) {
        float p = 0.0f;
        #pragma unroll
        for (int j = 0; j < 4; j++) {
            int o = tx * 4 + j;
            float tv = fmaxf(acc[i][j] + b1[o], 0.0f);
            p += tv * sw2[o];
        }
        atomicAdd(&ssum[ty * 4 + i], p);
    }
    __syncthreads();
    if (t < 32) {
        int i = rowBase + t;
        if (i < cnt) {
            int v = g_wlist[i];
            g_score[v] = ssum[t] + b2[0];
        }
    }
}

__global__ void k_out(const int* __restrict__ t_index, float* __restrict__ out) {
    int t = threadIdx.x;
    if (t >= 64) return;
    int b = t / 16;
    int v = t_index[t] + b * NN;
    out[t] = g_score[v];
}

// ------------------------- launch -------------------------
extern "C" void kernel_launch(void* const* d_in, const int* in_sizes, int n_in,
                              void* d_out, int out_size) {
    const int*   h_index   = (const int*)d_in[0];
    const int*   r_index   = (const int*)d_in[1];
    const int*   t_index   = (const int*)d_in[2];
    const float* hstates   = (const float*)d_in[3];
    // d_in[4] = rel_hidden_states (unused by forward)
    const int*   edge_idx  = (const int*)d_in[5];
    const int*   edge_attr = (const int*)d_in[6];
    const float* text      = (const float*)d_in[7];
    // d_in[8] = all_index (arange, structure known)
    const float* relT      = (const float*)d_in[9];
    const float* Wlin      = (const float*)d_in[10];
    const float* blin      = (const float*)d_in[11];
    const float* W1        = (const float*)d_in[12];
    const float* b1        = (const float*)d_in[13];
    const float* W2        = (const float*)d_in[14];
    const float* b2        = (const float*)d_in[15];
    const float* relw      = (const float*)d_in[16];
    const float* convW     = (const float*)d_in[17];
    const float* convb     = (const float*)d_in[18];
    float* out = (float*)d_out;

    k_init<<<157, 256>>>();
    k_count<<<391, 256>>>(edge_idx);
    k_scan<<<1, 1024>>>();
    k_scatter<<<391, 256>>>(edge_idx, edge_attr);
    k_inithidden<<<10000, 256>>>(text, h_index, hstates);
    k_repack<<<576, 256>>>(convW);
    k_qpart<<<1, 64>>>(r_index, relT, Wlin, blin);
    k_headscore<<<1, 128>>>(h_index, r_index, hstates, relT, Wlin, blin, W1, b1, W2, b2);

    for (int l = 0; l < 3; l++) {
        // node threshold (rank-4000)
        k_zero<<<256, 256>>>();
        k_hist<<<157, 256>>>(1, 0);
        k_pick<<<1, 1024>>>(1, 0, KS_N);
        k_hist<<<157, 256>>>(2, 0);
        k_pick<<<1, 1024>>>(2, 0, KS_N);
        // edge threshold (weighted rank-40000 over active nodes)
        k_zero<<<256, 256>>>();
        k_hist<<<157, 256>>>(1, 1);
        k_pick<<<1, 1024>>>(1, 1, ES_E);
        k_hist<<<157, 256>>>(2, 1);
        k_pick<<<1, 1024>>>(2, 1, ES_E);   // also resets g_wl
        // worklist of omask nodes, then aggregate/GEMM/apply/score
        k_worklist<<<157, 256>>>();
        k_agg<<<5000, 256>>>(relw, l);
        k_gemm<<<dim3(625, 3), 256>>>(l);
        k_apply<<<10000, 256>>>(convb, l);
        k_score1<<<625, 256>>>(Wlin);
        k_score2<<<1250, 256>>>(W1, b1, W2, b2);
    }
    k_out<<<1, 64>>>(t_index, out);
}